// round 1
// baseline (speedup 1.0000x reference)
#include <cuda_runtime.h>
#include <stdint.h>

#define B_TOT     16384
#define N_IN      6
#define N_MF      5
#define N_FUZZ    30
#define N_RULES   2048
#define NSPLIT    4
#define RPS       (N_RULES / NSPLIT)   // 512
#define TPB       128
#define BATCH_BLOCKS (B_TOT / TPB)     // 128
#define EPS_F     1e-12f

// Scratch (no allocation allowed in kernel_launch)
__device__ uint2  g_packed[N_RULES];
__device__ float2 g_ow[N_RULES];
__device__ float4 g_partial[NSPLIT * B_TOT];

// ---------------------------------------------------------------------------
// Prep: pack 6 rule indices (each <30) into 6 bytes; pre-gather out_centers.
// ---------------------------------------------------------------------------
__global__ void prep_kernel(const int* __restrict__ input_rules,
                            const int* __restrict__ output_rules,
                            const float* __restrict__ out_centers) {
    int r = blockIdx.x * blockDim.x + threadIdx.x;
    if (r >= N_RULES) return;
    const int* ir = input_rules + r * N_IN;
    unsigned w0 = (unsigned)ir[0] | ((unsigned)ir[1] << 8) |
                  ((unsigned)ir[2] << 16) | ((unsigned)ir[3] << 24);
    unsigned w1 = (unsigned)ir[4] | ((unsigned)ir[5] << 8);
    g_packed[r] = make_uint2(w0, w1);
    g_ow[r] = make_float2(out_centers[output_rules[r * 2 + 0]],
                          out_centers[output_rules[r * 2 + 1]]);
}

// ---------------------------------------------------------------------------
// Main: one thread = one batch element, one block-Y = one rule split.
// Fuzz table stored transposed in SMEM: s_fuzz[idx*TPB + tid]
//   -> bank = tid & 31 for every gather => conflict-free always.
// Rule reads are same-address across the warp => broadcast (free).
// ---------------------------------------------------------------------------
__global__ __launch_bounds__(TPB) void main_kernel(
    const float* __restrict__ x,
    const float* __restrict__ mf_centers,
    const float* __restrict__ mf_scales) {

    __shared__ float  s_fuzz[N_FUZZ * TPB];   // 15 KB
    __shared__ uint2  s_rules[RPS];           // 4 KB
    __shared__ float2 s_ow[RPS];              // 4 KB

    const int tid   = threadIdx.x;
    const int b     = blockIdx.x * TPB + tid;
    const int split = blockIdx.y;
    const int rbase = split * RPS;

    // Stage this split's rules into SMEM
    for (int k = tid; k < RPS; k += TPB) {
        s_rules[k] = g_packed[rbase + k];
        s_ow[k]    = g_ow[rbase + k];
    }

    // Fuzzify: 30 Gaussians for this batch element, stored transposed.
    float xv[N_IN];
    #pragma unroll
    for (int i = 0; i < N_IN; i++) xv[i] = x[b * N_IN + i];
    #pragma unroll
    for (int i = 0; i < N_IN; i++) {
        #pragma unroll
        for (int j = 0; j < N_MF; j++) {
            float c = __ldg(&mf_centers[i * N_MF + j]);
            float s = __ldg(&mf_scales[i * N_MF + j]);
            float z = __fdividef(xv[i] - c, s);
            s_fuzz[(i * N_MF + j) * TPB + tid] = __expf(-z * z);
        }
    }
    __syncthreads();

    const float* ft = s_fuzz + tid;
    float l1 = 0.f, d0 = 0.f, d1 = 0.f;

    #pragma unroll 4
    for (int k = 0; k < RPS; k++) {
        const uint2  pr = s_rules[k];   // broadcast LDS.64
        const float2 wv = s_ow[k];      // broadcast LDS.64

        float f0 = ft[(pr.x & 255u) * TPB];
        float f1 = ft[((pr.x >> 8)  & 255u) * TPB];
        float f2 = ft[((pr.x >> 16) & 255u) * TPB];
        float f3 = ft[(pr.x >> 24)          * TPB];
        float f4 = ft[(pr.y & 255u) * TPB];
        float f5 = ft[((pr.y >> 8)  & 255u) * TPB];

        float w = fminf(fminf(fminf(f0, f1), fminf(f2, f3)), fminf(f4, f5));

        l1 += w;                      // weights are >= 0 (exp), |w| == w
        d0 = fmaf(w, wv.x, d0);
        d1 = fmaf(w, wv.y, d1);
    }

    g_partial[split * B_TOT + b] = make_float4(l1, d0, d1, 0.f);
}

// ---------------------------------------------------------------------------
// Finalize: sum partials across splits, normalize, tanh affine, store float2.
// ---------------------------------------------------------------------------
__global__ void final_kernel(float* __restrict__ out) {
    int b = blockIdx.x * blockDim.x + threadIdx.x;
    if (b >= B_TOT) return;
    float l1 = 0.f, d0 = 0.f, d1 = 0.f;
    #pragma unroll
    for (int s = 0; s < NSPLIT; s++) {
        float4 p = g_partial[s * B_TOT + b];
        l1 += p.x; d0 += p.y; d1 += p.z;
    }
    float inv = __fdividef(1.0f, fmaxf(l1, EPS_F));
    float o0 = tanhf(d0 * inv) * 4.0f;           // scale 4.0, center 0.0
    float o1 = tanhf(d1 * inv) * 0.75f + 0.75f;  // scale 0.75, center 0.75
    reinterpret_cast<float2*>(out)[b] = make_float2(o0, o1);
}

// ---------------------------------------------------------------------------
extern "C" void kernel_launch(void* const* d_in, const int* in_sizes, int n_in,
                              void* d_out, int out_size) {
    const float* x           = (const float*)d_in[0];
    const float* mf_centers  = (const float*)d_in[1];
    const float* mf_scales   = (const float*)d_in[2];
    const float* out_centers = (const float*)d_in[3];
    const int*   input_rules = (const int*)d_in[4];
    const int*   output_rules= (const int*)d_in[5];

    prep_kernel<<<(N_RULES + 255) / 256, 256>>>(input_rules, output_rules, out_centers);

    dim3 grid(BATCH_BLOCKS, NSPLIT);
    main_kernel<<<grid, TPB>>>(x, mf_centers, mf_scales);

    final_kernel<<<(B_TOT + 255) / 256, 256>>>((float*)d_out);
}

// round 2
// speedup vs baseline: 2.0548x; 2.0548x over previous
#include <cuda_runtime.h>
#include <cuda_fp16.h>
#include <stdint.h>

#define B_TOT   16384
#define N_IN    6
#define N_MF    5
#define N_FUZZ  30
#define N_RULES 2048
#define NSPLIT  8
#define RPS     (N_RULES / NSPLIT)   // 256 rules per split
#define TPB     128
#define EPB     256                  // batch elems per block (2 per thread, half2-packed)
#define NGROUP  (B_TOT / EPB)        // 64 batch groups
#define EPS_F   1e-12f

// Scratch (__device__ globals: no allocation allowed)
__device__ float4 g_partial[NSPLIT * B_TOT];   // {l1, d0, d1, pad} per (split, elem)
__device__ int    g_cnt[NGROUP];               // zero-init; reset after each use

static __device__ __forceinline__ __half2 as_h2(uint32_t u) {
    return *reinterpret_cast<__half2*>(&u);
}

// ---------------------------------------------------------------------------
// Single fused kernel.
//  - grid = (NGROUP, NSPLIT). Block (g, s) processes batch elems
//    [g*256, g*256+256) against rules [s*256, (s+1)*256).
//  - Fuzz table in SMEM as half2: word (idx, tid) = {fuzz[b0], fuzz[b1]} with
//    b0 = g*256+tid, b1 = b0+128. One LDS.32 gather serves BOTH elems; bank =
//    tid mod 32 for every gather -> always conflict-free.
//  - Rules pre-packed into SMEM per block: 6 indices premultiplied by the
//    512-byte row stride as 3x(u16,u16), plus ow0 in the same uint4 (one
//    LDS.128 broadcast) and ow1 in a side array.
//  - Partials to global; last-arriving split block per group finalizes
//    (deterministic: fixed summation order) and resets the counter.
// ---------------------------------------------------------------------------
__global__ __launch_bounds__(TPB) void anfis_fused_kernel(
    const float* __restrict__ x,
    const float* __restrict__ mf_centers,
    const float* __restrict__ mf_scales,
    const float* __restrict__ out_centers,
    const int*   __restrict__ input_rules,
    const int*   __restrict__ output_rules,
    float* __restrict__ out)
{
    __shared__ __half2 s_fuzz[N_FUZZ * TPB];   // 15 KB
    __shared__ uint4   s_pk[RPS];              // 4 KB: {idx01, idx23, idx45, ow0bits}
    __shared__ float   s_ow1[RPS];             // 1 KB
    __shared__ int     s_flag;

    const int tid   = threadIdx.x;
    const int grp   = blockIdx.x;
    const int split = blockIdx.y;
    const int rbase = split * RPS;
    const int b0    = grp * EPB + tid;
    const int b1    = b0 + TPB;

    // ---- pack this split's rules into SMEM (premultiplied byte offsets) ----
    for (int k = tid; k < RPS; k += TPB) {
        const int r = rbase + k;
        const int* ir = input_rules + r * N_IN;
        unsigned p0 = (unsigned)ir[0] << 9;   // idx * 512B row stride (<= 14848)
        unsigned p1 = (unsigned)ir[1] << 9;
        unsigned p2 = (unsigned)ir[2] << 9;
        unsigned p3 = (unsigned)ir[3] << 9;
        unsigned p4 = (unsigned)ir[4] << 9;
        unsigned p5 = (unsigned)ir[5] << 9;
        float ow0 = out_centers[output_rules[r * 2 + 0]];
        float ow1 = out_centers[output_rules[r * 2 + 1]];
        s_pk[k]  = make_uint4(p0 | (p1 << 16), p2 | (p3 << 16), p4 | (p5 << 16),
                              __float_as_uint(ow0));
        s_ow1[k] = ow1;
    }

    // ---- fuzzify both batch elems, store as half2 pairs ----
    {
        float xa[N_IN], xb[N_IN];
        #pragma unroll
        for (int i = 0; i < N_IN; i++) {
            xa[i] = x[b0 * N_IN + i];
            xb[i] = x[b1 * N_IN + i];
        }
        #pragma unroll
        for (int i = 0; i < N_IN; i++) {
            #pragma unroll
            for (int j = 0; j < N_MF; j++) {
                float c  = __ldg(&mf_centers[i * N_MF + j]);
                float s  = __ldg(&mf_scales[i * N_MF + j]);
                float za = __fdividef(xa[i] - c, s);
                float zb = __fdividef(xb[i] - c, s);
                s_fuzz[(i * N_MF + j) * TPB + tid] =
                    __floats2half2_rn(__expf(-za * za), __expf(-zb * zb));
            }
        }
    }
    __syncthreads();

    // ---- rule loop: 6 half2 gathers, packed min, fp32 accumulation ----
    const char* fb = reinterpret_cast<const char*>(s_fuzz) + tid * 4;
    float l1a = 0.f, d0a = 0.f, d1a = 0.f;
    float l1b = 0.f, d0b = 0.f, d1b = 0.f;

    #pragma unroll 4
    for (int k = 0; k < RPS; k++) {
        const uint4 pk  = s_pk[k];                     // LDS.128 broadcast
        const float ow0 = __uint_as_float(pk.w);
        const float ow1 = s_ow1[k];                    // LDS.32 broadcast

        __half2 f0 = *reinterpret_cast<const __half2*>(fb + (pk.x & 0xFFFFu));
        __half2 f1 = *reinterpret_cast<const __half2*>(fb + (pk.x >> 16));
        __half2 f2 = *reinterpret_cast<const __half2*>(fb + (pk.y & 0xFFFFu));
        __half2 f3 = *reinterpret_cast<const __half2*>(fb + (pk.y >> 16));
        __half2 f4 = *reinterpret_cast<const __half2*>(fb + (pk.z & 0xFFFFu));
        __half2 f5 = *reinterpret_cast<const __half2*>(fb + (pk.z >> 16));

        __half2 w = __hmin2(__hmin2(__hmin2(f0, f1), __hmin2(f2, f3)),
                            __hmin2(f4, f5));
        float wa = __low2float(w);
        float wb = __high2float(w);

        l1a += wa;                    l1b += wb;       // weights >= 0
        d0a  = fmaf(wa, ow0, d0a);    d0b  = fmaf(wb, ow0, d0b);
        d1a  = fmaf(wa, ow1, d1a);    d1b  = fmaf(wb, ow1, d1b);
    }

    // ---- write partials ----
    g_partial[split * B_TOT + b0] = make_float4(l1a, d0a, d1a, 0.f);
    g_partial[split * B_TOT + b1] = make_float4(l1b, d0b, d1b, 0.f);

    // ---- last-block-done finalize (deterministic fixed-order summation) ----
    __threadfence();
    __syncthreads();
    if (tid == 0) {
        int old = atomicAdd(&g_cnt[grp], 1);
        s_flag = (old == NSPLIT - 1);
    }
    __syncthreads();

    if (s_flag) {
        __threadfence();
        #pragma unroll
        for (int e = 0; e < 2; e++) {
            const int b = (e == 0) ? b0 : b1;
            float l1 = 0.f, d0 = 0.f, d1 = 0.f;
            #pragma unroll
            for (int s = 0; s < NSPLIT; s++) {
                float4 p = __ldcg(&g_partial[s * B_TOT + b]);
                l1 += p.x; d0 += p.y; d1 += p.z;
            }
            float inv = __fdividef(1.0f, fmaxf(l1, EPS_F));
            float o0 = tanhf(d0 * inv) * 4.0f;            // scale 4.0, center 0.0
            float o1 = tanhf(d1 * inv) * 0.75f + 0.75f;   // scale .75, center .75
            reinterpret_cast<float2*>(out)[b] = make_float2(o0, o1);
        }
        if (tid == 0) g_cnt[grp] = 0;   // reset for next graph replay
    }
}

// ---------------------------------------------------------------------------
extern "C" void kernel_launch(void* const* d_in, const int* in_sizes, int n_in,
                              void* d_out, int out_size) {
    const float* x            = (const float*)d_in[0];
    const float* mf_centers   = (const float*)d_in[1];
    const float* mf_scales    = (const float*)d_in[2];
    const float* out_centers  = (const float*)d_in[3];
    const int*   input_rules  = (const int*)d_in[4];
    const int*   output_rules = (const int*)d_in[5];

    dim3 grid(NGROUP, NSPLIT);
    anfis_fused_kernel<<<grid, TPB>>>(x, mf_centers, mf_scales, out_centers,
                                      input_rules, output_rules, (float*)d_out);
}